// round 5
// baseline (speedup 1.0000x reference)
#include <cuda_runtime.h>
#include <cuda_bf16.h>
#include <stdint.h>
#include <stddef.h>

#define DEVFN __device__ __forceinline__

// ---------------- problem constants ----------------
#define NROWS   8192
#define K_DIM   512
#define MT      128
#define NT      128
#define KC      64          // K per chunk
#define NCHUNK  8           // K_DIM / KC
#define THREADS 256

#define TILE_BYTES   (128 * 128)          // one 128x64 bf16 tile, 128B rows
#define STAGE_BYTES  (4 * TILE_BYTES)     // Ah, Al, Bh, Bl = 64KB
#define SMEM_TOTAL   (2 * STAGE_BYTES)    // 131072

// ---------------- device scratch (normalized hi/lo splits) ----------------
__device__ __nv_bfloat16 g_h1[(size_t)NROWS * K_DIM];
__device__ __nv_bfloat16 g_l1[(size_t)NROWS * K_DIM];
__device__ __nv_bfloat16 g_h2[(size_t)NROWS * K_DIM];
__device__ __nv_bfloat16 g_l2[(size_t)NROWS * K_DIM];

// ---------------- helpers ----------------
DEVFN uint32_t smem_u32(const void* p) {
    uint32_t a;
    asm("{ .reg .u64 t; cvta.to.shared.u64 t, %1; cvt.u32.u64 %0, t; }"
        : "=r"(a) : "l"(p));
    return a;
}

template<int N> DEVFN void cp_wait_group() {
    asm volatile("cp.async.wait_group %0;" :: "n"(N) : "memory");
}

DEVFN uint32_t sw(uint32_t off) {            // SW128 XOR swizzle, 16B granular
    return off ^ ((off >> 3) & 0x70);
}

DEVFN void ldsm_x4(uint32_t* r, uint32_t addr) {
    asm volatile("ldmatrix.sync.aligned.m8n8.x4.shared.b16 {%0,%1,%2,%3}, [%4];"
        : "=r"(r[0]), "=r"(r[1]), "=r"(r[2]), "=r"(r[3]) : "r"(addr));
}

DEVFN void mma16816(float* d, const uint32_t* a, const uint32_t* b) {
    asm volatile(
        "mma.sync.aligned.m16n8k16.row.col.f32.bf16.bf16.f32 "
        "{%0,%1,%2,%3}, {%4,%5,%6,%7}, {%8,%9}, {%0,%1,%2,%3};"
        : "+f"(d[0]), "+f"(d[1]), "+f"(d[2]), "+f"(d[3])
        : "r"(a[0]), "r"(a[1]), "r"(a[2]), "r"(a[3]), "r"(b[0]), "r"(b[1]));
}

// Load one 128x64 bf16 tile (rows rowbase.., cols kofs..kofs+63) into swizzled SMEM.
DEVFN void load_tile(uint32_t dst_base, const __nv_bfloat16* __restrict__ src,
                     int rowbase, int kofs, int tid) {
#pragma unroll
    for (int j = 0; j < 4; j++) {
        int idx  = j * THREADS + tid;        // 0..1023 (16B units)
        int row  = idx >> 3;                 // 0..127
        int c16  = idx & 7;                  // 16B chunk within 128B row
        const void* g = (const void*)(src + (size_t)(rowbase + row) * K_DIM + kofs + c16 * 8);
        uint32_t d = dst_base + sw((uint32_t)(row * 128 + c16 * 16));
        asm volatile("cp.async.cg.shared.global [%0], [%1], 16;" :: "r"(d), "l"(g));
    }
}

DEVFN void load_chunk(uint32_t smem_base, int tid, int m0, int n0, int c, int s) {
    const uint32_t sb = smem_base + s * STAGE_BYTES;
    const int kofs = c * KC;
    load_tile(sb + 0 * TILE_BYTES, g_h2, m0, kofs, tid);   // A hi (x2 rows)
    load_tile(sb + 1 * TILE_BYTES, g_l2, m0, kofs, tid);   // A lo
    load_tile(sb + 2 * TILE_BYTES, g_h1, n0, kofs, tid);   // B hi (x1 rows)
    load_tile(sb + 3 * TILE_BYTES, g_l1, n0, kofs, tid);   // B lo
    asm volatile("cp.async.commit_group;" ::: "memory");
}

// ---------------- kernel 1: per-row normalize + bf16 hi/lo split ----------------
__global__ void __launch_bounds__(128) norm_split_kernel(const float* __restrict__ x, int which) {
    __shared__ float ws[4];
    const int row = blockIdx.x;
    const int t = threadIdx.x;
    float4 v = reinterpret_cast<const float4*>(x + (size_t)row * K_DIM)[t];
    float ss = v.x * v.x + v.y * v.y + v.z * v.z + v.w * v.w;
#pragma unroll
    for (int o = 16; o; o >>= 1) ss += __shfl_xor_sync(0xffffffffu, ss, o);
    if ((t & 31) == 0) ws[t >> 5] = ss;
    __syncthreads();
    float tot = ws[0] + ws[1] + ws[2] + ws[3];
    float scale = rsqrtf(fmaxf(tot, 1e-24f));

    __nv_bfloat16* H = which ? g_h2 : g_h1;
    __nv_bfloat16* L = which ? g_l2 : g_l1;

    float y[4] = {v.x * scale, v.y * scale, v.z * scale, v.w * scale};
    unsigned short hh[4], ll[4];
#pragma unroll
    for (int i = 0; i < 4; i++) {
        __nv_bfloat16 h = __float2bfloat16(y[i]);
        float r = y[i] - __bfloat162float(h);
        __nv_bfloat16 l = __float2bfloat16(r);
        hh[i] = *reinterpret_cast<unsigned short*>(&h);
        ll[i] = *reinterpret_cast<unsigned short*>(&l);
    }
    reinterpret_cast<ushort4*>(H + (size_t)row * K_DIM)[t] = make_ushort4(hh[0], hh[1], hh[2], hh[3]);
    reinterpret_cast<ushort4*>(L + (size_t)row * K_DIM)[t] = make_ushort4(ll[0], ll[1], ll[2], ll[3]);
}

// ---------------- kernel 2: mma.sync 3-term split GEMM ----------------
// 8 warps: wm = wid&3 (M), wn = wid>>2 (N). Warp tile 32(M) x 64(N).
__global__ void __launch_bounds__(THREADS, 1) cosine_gemm_kernel(float* __restrict__ out) {
    extern __shared__ char smem[];
    const uint32_t smem_base = smem_u32(smem);
    const int tid  = threadIdx.x;
    const int wid  = tid >> 5;
    const int lane = tid & 31;
    const int wm = wid & 3;
    const int wn = wid >> 2;

    const int m0 = blockIdx.y * MT;
    const int n0 = blockIdx.x * NT;

    float acc[2][8][4];
#pragma unroll
    for (int i = 0; i < 2; i++)
#pragma unroll
        for (int j = 0; j < 8; j++)
#pragma unroll
            for (int k = 0; k < 4; k++) acc[i][j][k] = 0.0f;

    // per-thread ldmatrix base offsets (bytes within a tile, before k-step add)
    // A: lanes 0-15 -> rows 0-15, lanes 16-31 -> same rows, k+8 (16B col 1)
    uint32_t offA[2];
#pragma unroll
    for (int mi = 0; mi < 2; mi++) {
        int row = wm * 32 + mi * 16 + (lane & 15);
        offA[mi] = (uint32_t)(row * 128 + ((lane >> 4) & 1) * 16);
    }
    // B: lanes 0-7: n0-7 k0 | 8-15: n0-7 k8 | 16-23: n8-15 k0 | 24-31: n8-15 k8
    uint32_t offB[4];
#pragma unroll
    for (int nj = 0; nj < 4; nj++) {
        int row = wn * 64 + nj * 16 + (lane & 7) + ((lane >> 4) & 1) * 8;
        offB[nj] = (uint32_t)(row * 128 + ((lane >> 3) & 1) * 16);
    }

    // prologue: prefetch chunks 0, 1
    load_chunk(smem_base, tid, m0, n0, 0, 0);
    load_chunk(smem_base, tid, m0, n0, 1, 1);

#pragma unroll 1
    for (int i = 0; i < NCHUNK; i++) {
        const int s = i & 1;
        if (i < NCHUNK - 1) cp_wait_group<1>(); else cp_wait_group<0>();
        __syncthreads();

        const uint32_t sb  = smem_base + s * STAGE_BYTES;
        const uint32_t bAh = sb + 0 * TILE_BYTES;
        const uint32_t bAl = sb + 1 * TILE_BYTES;
        const uint32_t bBh = sb + 2 * TILE_BYTES;
        const uint32_t bBl = sb + 3 * TILE_BYTES;

#pragma unroll
        for (int kk = 0; kk < 4; kk++) {          // 4 x k16 per chunk
            const uint32_t kofs = kk * 32;        // 16 bf16 = 32B
            uint32_t ah[2][4], al[2][4], bh[4][4], bl[4][4];
#pragma unroll
            for (int mi = 0; mi < 2; mi++) {
                ldsm_x4(ah[mi], bAh + sw(offA[mi] + kofs));
                ldsm_x4(al[mi], bAl + sw(offA[mi] + kofs));
            }
#pragma unroll
            for (int nj = 0; nj < 4; nj++) {
                ldsm_x4(bh[nj], bBh + sw(offB[nj] + kofs));
                ldsm_x4(bl[nj], bBl + sw(offB[nj] + kofs));
            }
#pragma unroll
            for (int mi = 0; mi < 2; mi++)
#pragma unroll
                for (int nj = 0; nj < 4; nj++)
#pragma unroll
                    for (int h = 0; h < 2; h++) {
                        float* d = acc[mi][nj * 2 + h];
                        mma16816(d, ah[mi], &bh[nj][h * 2]);   // Ah*Bh
                        mma16816(d, ah[mi], &bl[nj][h * 2]);   // Ah*Bl
                        mma16816(d, al[mi], &bh[nj][h * 2]);   // Al*Bh
                    }
        }

        __syncthreads();   // all warps done reading stage s before refill
        if (i + 2 < NCHUNK) load_chunk(smem_base, tid, m0, n0, i + 2, s);
    }

    // epilogue: direct float2 stores (32B-sector aligned per 4-lane group)
    const int rbase = m0 + wm * 32 + (lane >> 2);
    const int cbase = n0 + wn * 64 + 2 * (lane & 3);
#pragma unroll
    for (int mi = 0; mi < 2; mi++)
#pragma unroll
        for (int j = 0; j < 8; j++) {
            int row = rbase + mi * 16;
            int col = cbase + j * 8;
            float2 v0 = make_float2(acc[mi][j][0], acc[mi][j][1]);
            float2 v1 = make_float2(acc[mi][j][2], acc[mi][j][3]);
            *reinterpret_cast<float2*>(out + (size_t)row * NROWS + col) = v0;
            *reinterpret_cast<float2*>(out + (size_t)(row + 8) * NROWS + col) = v1;
        }
}

// ---------------- launch ----------------
extern "C" void kernel_launch(void* const* d_in, const int* in_sizes, int n_in,
                              void* d_out, int out_size) {
    const float* x1 = (const float*)d_in[0];
    const float* x2 = (const float*)d_in[1];
    float* out = (float*)d_out;

    cudaFuncSetAttribute(cosine_gemm_kernel,
                         cudaFuncAttributeMaxDynamicSharedMemorySize, SMEM_TOTAL);

    norm_split_kernel<<<NROWS, 128>>>(x1, 0);
    norm_split_kernel<<<NROWS, 128>>>(x2, 1);

    dim3 grid(NROWS / NT, NROWS / MT);
    cosine_gemm_kernel<<<grid, THREADS, SMEM_TOTAL>>>(out);
}

// round 6
// speedup vs baseline: 1.6722x; 1.6722x over previous
#include <cuda_runtime.h>
#include <cuda_fp16.h>
#include <stdint.h>
#include <stddef.h>

#define DEVFN __device__ __forceinline__

// ---------------- problem constants ----------------
#define NROWS   8192
#define K_DIM   512
#define MT      128
#define NT      128
#define KC      64          // K per chunk
#define NCHUNK  8           // K_DIM / KC
#define THREADS 256
#define NSTAGE  3

#define TILE_BYTES   (128 * 128)          // one 128x64 fp16 tile, 128B rows
#define STAGE_BYTES  (2 * TILE_BYTES)     // A, B = 32KB
#define SMEM_TOTAL   (NSTAGE * STAGE_BYTES)   // 98304

// ---------------- device scratch (normalized fp16) ----------------
__device__ __half g_h1[(size_t)NROWS * K_DIM];
__device__ __half g_h2[(size_t)NROWS * K_DIM];

// ---------------- helpers ----------------
DEVFN uint32_t smem_u32(const void* p) {
    uint32_t a;
    asm("{ .reg .u64 t; cvta.to.shared.u64 t, %1; cvt.u32.u64 %0, t; }"
        : "=r"(a) : "l"(p));
    return a;
}

template<int N> DEVFN void cp_wait_group() {
    asm volatile("cp.async.wait_group %0;" :: "n"(N) : "memory");
}

DEVFN uint32_t sw(uint32_t off) {            // SW128 XOR swizzle, 16B granular
    return off ^ ((off >> 3) & 0x70);
}

DEVFN void ldsm_x4(uint32_t* r, uint32_t addr) {
    asm volatile("ldmatrix.sync.aligned.m8n8.x4.shared.b16 {%0,%1,%2,%3}, [%4];"
        : "=r"(r[0]), "=r"(r[1]), "=r"(r[2]), "=r"(r[3]) : "r"(addr));
}

DEVFN void mma16816(float* d, const uint32_t* a, const uint32_t* b) {
    asm volatile(
        "mma.sync.aligned.m16n8k16.row.col.f32.f16.f16.f32 "
        "{%0,%1,%2,%3}, {%4,%5,%6,%7}, {%8,%9}, {%0,%1,%2,%3};"
        : "+f"(d[0]), "+f"(d[1]), "+f"(d[2]), "+f"(d[3])
        : "r"(a[0]), "r"(a[1]), "r"(a[2]), "r"(a[3]), "r"(b[0]), "r"(b[1]));
}

// Load one 128x64 fp16 tile (rows rowbase.., cols kofs..kofs+63) into swizzled SMEM.
DEVFN void load_tile(uint32_t dst_base, const __half* __restrict__ src,
                     int rowbase, int kofs, int tid) {
#pragma unroll
    for (int j = 0; j < 4; j++) {
        int idx  = j * THREADS + tid;        // 0..1023 (16B units)
        int row  = idx >> 3;                 // 0..127
        int c16  = idx & 7;                  // 16B chunk within 128B row
        const void* g = (const void*)(src + (size_t)(rowbase + row) * K_DIM + kofs + c16 * 8);
        uint32_t d = dst_base + sw((uint32_t)(row * 128 + c16 * 16));
        asm volatile("cp.async.cg.shared.global [%0], [%1], 16;" :: "r"(d), "l"(g));
    }
}

DEVFN void load_chunk(uint32_t smem_base, int tid, int m0, int n0, int c) {
    const uint32_t sb = smem_base + (c % NSTAGE) * STAGE_BYTES;
    const int kofs = c * KC;
    load_tile(sb + 0 * TILE_BYTES, g_h2, m0, kofs, tid);   // A (x2 rows)
    load_tile(sb + 1 * TILE_BYTES, g_h1, n0, kofs, tid);   // B (x1 rows)
    asm volatile("cp.async.commit_group;" ::: "memory");
}

// ---------------- kernel 1: per-row normalize -> fp16 ----------------
__global__ void __launch_bounds__(128) norm_split_kernel(const float* __restrict__ x, int which) {
    __shared__ float ws[4];
    const int row = blockIdx.x;
    const int t = threadIdx.x;
    float4 v = reinterpret_cast<const float4*>(x + (size_t)row * K_DIM)[t];
    float ss = v.x * v.x + v.y * v.y + v.z * v.z + v.w * v.w;
#pragma unroll
    for (int o = 16; o; o >>= 1) ss += __shfl_xor_sync(0xffffffffu, ss, o);
    if ((t & 31) == 0) ws[t >> 5] = ss;
    __syncthreads();
    float tot = ws[0] + ws[1] + ws[2] + ws[3];
    float scale = rsqrtf(fmaxf(tot, 1e-24f));

    __half* H = which ? g_h2 : g_h1;
    __half2 a = __floats2half2_rn(v.x * scale, v.y * scale);
    __half2 b = __floats2half2_rn(v.z * scale, v.w * scale);
    uint32_t ua = *reinterpret_cast<uint32_t*>(&a);
    uint32_t ub = *reinterpret_cast<uint32_t*>(&b);
    reinterpret_cast<uint2*>(H + (size_t)row * K_DIM)[t] = make_uint2(ua, ub);
}

// ---------------- kernel 2: fp16 mma.sync GEMM ----------------
// 8 warps: wm = wid&3 (M), wn = wid>>2 (N). Warp tile 32(M) x 64(N).
__global__ void __launch_bounds__(THREADS, 2) cosine_gemm_kernel(float* __restrict__ out) {
    extern __shared__ char smem[];
    const uint32_t smem_base = smem_u32(smem);
    const int tid  = threadIdx.x;
    const int wid  = tid >> 5;
    const int lane = tid & 31;
    const int wm = wid & 3;
    const int wn = wid >> 2;

    const int m0 = blockIdx.y * MT;
    const int n0 = blockIdx.x * NT;

    float acc[2][8][4];
#pragma unroll
    for (int i = 0; i < 2; i++)
#pragma unroll
        for (int j = 0; j < 8; j++)
#pragma unroll
            for (int k = 0; k < 4; k++) acc[i][j][k] = 0.0f;

    // per-thread ldmatrix base offsets (bytes within a tile, before k-step add)
    uint32_t offA[2];
#pragma unroll
    for (int mi = 0; mi < 2; mi++) {
        int row = wm * 32 + mi * 16 + (lane & 15);
        offA[mi] = (uint32_t)(row * 128 + ((lane >> 4) & 1) * 16);
    }
    uint32_t offB[4];
#pragma unroll
    for (int nj = 0; nj < 4; nj++) {
        int row = wn * 64 + nj * 16 + (lane & 7) + ((lane >> 4) & 1) * 8;
        offB[nj] = (uint32_t)(row * 128 + ((lane >> 3) & 1) * 16);
    }

    // prologue: prefetch chunks 0, 1, 2
    load_chunk(smem_base, tid, m0, n0, 0);
    load_chunk(smem_base, tid, m0, n0, 1);
    load_chunk(smem_base, tid, m0, n0, 2);

#pragma unroll 1
    for (int i = 0; i < NCHUNK; i++) {
        if (i <= NCHUNK - 3)      cp_wait_group<2>();
        else if (i == NCHUNK - 2) cp_wait_group<1>();
        else                      cp_wait_group<0>();
        __syncthreads();

        const uint32_t sb = smem_base + (i % NSTAGE) * STAGE_BYTES;
        const uint32_t bA = sb;
        const uint32_t bB = sb + TILE_BYTES;

#pragma unroll
        for (int kk = 0; kk < 4; kk++) {          // 4 x k16 per chunk
            const uint32_t kofs = kk * 32;        // 16 fp16 = 32B
            uint32_t a[2][4];
#pragma unroll
            for (int mi = 0; mi < 2; mi++)
                ldsm_x4(a[mi], bA + sw(offA[mi] + kofs));
#pragma unroll
            for (int nj = 0; nj < 4; nj++) {
                uint32_t b[4];
                ldsm_x4(b, bB + sw(offB[nj] + kofs));
#pragma unroll
                for (int mi = 0; mi < 2; mi++) {
                    mma16816(acc[mi][nj * 2 + 0], a[mi], &b[0]);
                    mma16816(acc[mi][nj * 2 + 1], a[mi], &b[2]);
                }
            }
        }

        __syncthreads();   // all warps done reading this stage before refill
        if (i + 3 < NCHUNK) load_chunk(smem_base, tid, m0, n0, i + 3);
    }

    // epilogue: direct float2 stores (32B-sector aligned per 4-lane group)
    const int rbase = m0 + wm * 32 + (lane >> 2);
    const int cbase = n0 + wn * 64 + 2 * (lane & 3);
#pragma unroll
    for (int mi = 0; mi < 2; mi++)
#pragma unroll
        for (int j = 0; j < 8; j++) {
            int row = rbase + mi * 16;
            int col = cbase + j * 8;
            float2 v0 = make_float2(acc[mi][j][0], acc[mi][j][1]);
            float2 v1 = make_float2(acc[mi][j][2], acc[mi][j][3]);
            *reinterpret_cast<float2*>(out + (size_t)row * NROWS + col) = v0;
            *reinterpret_cast<float2*>(out + (size_t)(row + 8) * NROWS + col) = v1;
        }
}

// ---------------- launch ----------------
extern "C" void kernel_launch(void* const* d_in, const int* in_sizes, int n_in,
                              void* d_out, int out_size) {
    const float* x1 = (const float*)d_in[0];
    const float* x2 = (const float*)d_in[1];
    float* out = (float*)d_out;

    cudaFuncSetAttribute(cosine_gemm_kernel,
                         cudaFuncAttributeMaxDynamicSharedMemorySize, SMEM_TOTAL);

    norm_split_kernel<<<NROWS, 128>>>(x1, 0);
    norm_split_kernel<<<NROWS, 128>>>(x2, 1);

    dim3 grid(NROWS / NT, NROWS / MT);
    cosine_gemm_kernel<<<grid, THREADS, SMEM_TOTAL>>>(out);
}

// round 9
// speedup vs baseline: 2.3846x; 1.4260x over previous
#include <cuda_runtime.h>
#include <cuda_fp16.h>
#include <stdint.h>
#include <stddef.h>

#define DEVFN __device__ __forceinline__

// ---------------- problem constants ----------------
#define NROWS   8192
#define K_DIM   512
#define MT      256
#define NT      128
#define KC      64          // K per chunk
#define NCHUNK  8           // K_DIM / KC
#define THREADS 256
#define NSTAGE  4

#define A_TILE_BYTES (MT * 128)           // 256x64 fp16, 128B rows = 32KB
#define B_TILE_BYTES (NT * 128)           // 128x64 fp16 = 16KB
#define STAGE_BYTES  (A_TILE_BYTES + B_TILE_BYTES)   // 48KB
#define SMEM_TOTAL   (NSTAGE * STAGE_BYTES)          // 196608

// ---------------- device scratch (normalized fp16) ----------------
__device__ __half g_h1[(size_t)NROWS * K_DIM];
__device__ __half g_h2[(size_t)NROWS * K_DIM];

// ---------------- helpers ----------------
DEVFN uint32_t smem_u32(const void* p) {
    uint32_t a;
    asm("{ .reg .u64 t; cvta.to.shared.u64 t, %1; cvt.u32.u64 %0, t; }"
        : "=r"(a) : "l"(p));
    return a;
}

template<int N> DEVFN void cp_wait_group() {
    asm volatile("cp.async.wait_group %0;" :: "n"(N) : "memory");
}

DEVFN uint32_t sw(uint32_t off) {            // SW128 XOR swizzle, 16B granular
    return off ^ ((off >> 3) & 0x70);
}

DEVFN void ldsm_x4(uint32_t* r, uint32_t addr) {
    asm volatile("ldmatrix.sync.aligned.m8n8.x4.shared.b16 {%0,%1,%2,%3}, [%4];"
        : "=r"(r[0]), "=r"(r[1]), "=r"(r[2]), "=r"(r[3]) : "r"(addr));
}

DEVFN void mma16816(float* d, const uint32_t* a, const uint32_t* b) {
    asm volatile(
        "mma.sync.aligned.m16n8k16.row.col.f32.f16.f16.f32 "
        "{%0,%1,%2,%3}, {%4,%5,%6,%7}, {%8,%9}, {%0,%1,%2,%3};"
        : "+f"(d[0]), "+f"(d[1]), "+f"(d[2]), "+f"(d[3])
        : "r"(a[0]), "r"(a[1]), "r"(a[2]), "r"(a[3]), "r"(b[0]), "r"(b[1]));
}

// Load a ROWSxKC fp16 tile (rows rowbase.., cols kofs..+63) into swizzled SMEM.
template<int ROWS>
DEVFN void load_tile(uint32_t dst_base, const __half* __restrict__ src,
                     int rowbase, int kofs, int tid) {
#pragma unroll
    for (int j = 0; j < ROWS * 8 / THREADS; j++) {
        int idx  = j * THREADS + tid;        // 16B units
        int row  = idx >> 3;
        int c16  = idx & 7;
        const void* g = (const void*)(src + (size_t)(rowbase + row) * K_DIM + kofs + c16 * 8);
        uint32_t d = dst_base + sw((uint32_t)(row * 128 + c16 * 16));
        asm volatile("cp.async.cg.shared.global [%0], [%1], 16;" :: "r"(d), "l"(g));
    }
}

DEVFN void load_chunk(uint32_t smem_base, int tid, int m0, int n0, int c) {
    const uint32_t sb = smem_base + (c & (NSTAGE - 1)) * STAGE_BYTES;
    const int kofs = c * KC;
    load_tile<MT>(sb, g_h2, m0, kofs, tid);                 // A (x2 rows)
    load_tile<NT>(sb + A_TILE_BYTES, g_h1, n0, kofs, tid);  // B (x1 rows)
    asm volatile("cp.async.commit_group;" ::: "memory");
}

// ---------------- kernel 1: per-row normalize -> fp16 (both inputs) ----------------
__global__ void __launch_bounds__(128) norm_split_kernel(const float* __restrict__ x1,
                                                         const float* __restrict__ x2) {
    __shared__ float ws[4];
    const int b = blockIdx.x;
    const int row = b & (NROWS - 1);
    const float* x = (b < NROWS) ? x1 : x2;
    __half* H = (b < NROWS) ? g_h1 : g_h2;
    const int t = threadIdx.x;
    float4 v = reinterpret_cast<const float4*>(x + (size_t)row * K_DIM)[t];
    float ss = v.x * v.x + v.y * v.y + v.z * v.z + v.w * v.w;
#pragma unroll
    for (int o = 16; o; o >>= 1) ss += __shfl_xor_sync(0xffffffffu, ss, o);
    if ((t & 31) == 0) ws[t >> 5] = ss;
    __syncthreads();
    float tot = ws[0] + ws[1] + ws[2] + ws[3];
    float scale = rsqrtf(fmaxf(tot, 1e-24f));

    __half2 a = __floats2half2_rn(v.x * scale, v.y * scale);
    __half2 c = __floats2half2_rn(v.z * scale, v.w * scale);
    uint32_t ua = *reinterpret_cast<uint32_t*>(&a);
    uint32_t uc = *reinterpret_cast<uint32_t*>(&c);
    reinterpret_cast<uint2*>(H + (size_t)row * K_DIM)[t] = make_uint2(ua, uc);
}

// ---------------- kernel 2: fp16 mma.sync GEMM, 256x128 CTA tile ----------------
// 8 warps: wm = wid&3 (M, 4 x 64), wn = wid>>2 (N, 2 x 64). Warp tile 64x64.
__global__ void __launch_bounds__(THREADS, 1) cosine_gemm_kernel(float* __restrict__ out) {
    extern __shared__ char smem[];
    const uint32_t smem_base = smem_u32(smem);
    const int tid  = threadIdx.x;
    const int wid  = tid >> 5;
    const int lane = tid & 31;
    const int wm = wid & 3;
    const int wn = wid >> 2;

    const int m0 = blockIdx.y * MT;
    const int n0 = blockIdx.x * NT;

    float acc[4][8][4];
#pragma unroll
    for (int i = 0; i < 4; i++)
#pragma unroll
        for (int j = 0; j < 8; j++)
#pragma unroll
            for (int k = 0; k < 4; k++) acc[i][j][k] = 0.0f;

    // per-thread ldmatrix base offsets (bytes within a tile, before k-step add)
    uint32_t offA[4];
#pragma unroll
    for (int mi = 0; mi < 4; mi++) {
        int row = wm * 64 + mi * 16 + (lane & 15);
        offA[mi] = (uint32_t)(row * 128 + ((lane >> 4) & 1) * 16);
    }
    uint32_t offB[4];
#pragma unroll
    for (int nj = 0; nj < 4; nj++) {
        int row = wn * 64 + nj * 16 + (lane & 7) + ((lane >> 4) & 1) * 8;
        offB[nj] = (uint32_t)(row * 128 + ((lane >> 3) & 1) * 16);
    }

    // prologue: prefetch chunks 0, 1, 2
    load_chunk(smem_base, tid, m0, n0, 0);
    load_chunk(smem_base, tid, m0, n0, 1);
    load_chunk(smem_base, tid, m0, n0, 2);

#pragma unroll 1
    for (int i = 0; i < NCHUNK; i++) {
        if (i <= NCHUNK - 3)      cp_wait_group<2>();
        else if (i == NCHUNK - 2) cp_wait_group<1>();
        else                      cp_wait_group<0>();
        __syncthreads();
        // refill: stage (i+3)%4 holds chunk i-1, fully consumed before the bar above
        if (i + 3 < NCHUNK) load_chunk(smem_base, tid, m0, n0, i + 3);

        const uint32_t sb = smem_base + (i & (NSTAGE - 1)) * STAGE_BYTES;
        const uint32_t bA = sb;
        const uint32_t bB = sb + A_TILE_BYTES;

#pragma unroll
        for (int kk = 0; kk < 4; kk++) {          // 4 x k16 per chunk
            const uint32_t kofs = kk * 32;        // 16 fp16 = 32B
            uint32_t a[4][4];
#pragma unroll
            for (int mi = 0; mi < 4; mi++)
                ldsm_x4(a[mi], bA + sw(offA[mi] + kofs));
#pragma unroll
            for (int nj = 0; nj < 4; nj++) {
                uint32_t b[4];
                ldsm_x4(b, bB + sw(offB[nj] + kofs));
#pragma unroll
                for (int mi = 0; mi < 4; mi++) {
                    mma16816(acc[mi][nj * 2 + 0], a[mi], &b[0]);
                    mma16816(acc[mi][nj * 2 + 1], a[mi], &b[2]);
                }
            }
        }
    }

    // epilogue: direct float2 stores (32B-sector aligned per 4-lane group)
    const int rbase = m0 + wm * 64 + (lane >> 2);
    const int cbase = n0 + wn * 64 + 2 * (lane & 3);
#pragma unroll
    for (int mi = 0; mi < 4; mi++)
#pragma unroll
        for (int j = 0; j < 8; j++) {
            int row = rbase + mi * 16;
            int col = cbase + j * 8;
            float2 v0 = make_float2(acc[mi][j][0], acc[mi][j][1]);
            float2 v1 = make_float2(acc[mi][j][2], acc[mi][j][3]);
            *reinterpret_cast<float2*>(out + (size_t)row * NROWS + col) = v0;
            *reinterpret_cast<float2*>(out + (size_t)(row + 8) * NROWS + col) = v1;
        }
}

// ---------------- launch ----------------
extern "C" void kernel_launch(void* const* d_in, const int* in_sizes, int n_in,
                              void* d_out, int out_size) {
    const float* x1 = (const float*)d_in[0];
    const float* x2 = (const float*)d_in[1];
    float* out = (float*)d_out;

    cudaFuncSetAttribute(cosine_gemm_kernel,
                         cudaFuncAttributeMaxDynamicSharedMemorySize, SMEM_TOTAL);

    norm_split_kernel<<<2 * NROWS, 128>>>(x1, x2);

    dim3 grid(NROWS / NT, NROWS / MT);
    cosine_gemm_kernel<<<grid, THREADS, SMEM_TOTAL>>>(out);
}